// round 13
// baseline (speedup 1.0000x reference)
#include <cuda_runtime.h>
#include <cuda_bf16.h>
#include <stdint.h>

#define IN_F   4096
#define OUT_F  11008
#define BATCH  16
#define SPLITS 4
#define KSTEPS_TOT   (IN_F / 16)            // 256 k16-steps
#define KSTEPS_SPLIT (KSTEPS_TOT / SPLITS)  // 64
#define CKS    8                            // ksteps per smem chunk
#define NCHUNK (KSTEPS_SPLIT / CKS)         // 8
#define MTILE  64
#define THREADS 128

// Static scratch (allocations forbidden).
__device__ __align__(16) float g_part[SPLITS * BATCH * OUT_F];    // [s][b][o]

// Pack two floats into one bf16x2 reg (low = first).
__device__ __forceinline__ uint32_t pack_bf16x2(float ev, float od) {
    __nv_bfloat162 h = __floats2bfloat162_rn(ev, od);   // .x = ev (low), .y = od (high)
    return *(uint32_t*)&h;
}

__device__ __forceinline__ float bf_round(float v) {
    return __bfloat162float(__float2bfloat16(v));
}

// m16n8k16 row.col bf16 MMA, fp32 accumulate in place.
__device__ __forceinline__ void mma16816(float* c, const uint32_t* a, uint32_t b0, uint32_t b1) {
    asm volatile(
        "mma.sync.aligned.m16n8k16.row.col.f32.bf16.bf16.f32 "
        "{%0,%1,%2,%3}, {%4,%5,%6,%7}, {%8,%9}, {%0,%1,%2,%3};"
        : "+f"(c[0]), "+f"(c[1]), "+f"(c[2]), "+f"(c[3])
        : "r"(a[0]), "r"(a[1]), "r"(a[2]), "r"(a[3]), "r"(b0), "r"(b1));
}

// Build one B-stage uint4 directly from x.
// u = stage-word index within chunk (0..511). Components e=0..3 share one
// batch row and 8 consecutive k floats. ksc = absolute kstep of chunk start.
__device__ __forceinline__ uint4 make_bstage(const float* __restrict__ x, int ksc, int u) {
    int ks_loc = u >> 6;
    int r  = (u >> 3) & 7;
    int g  = u & 7;
    int jj = r >> 1, p = r & 1;
    int br = (jj & 1) * 8 + g;
    int kb = (ksc + ks_loc) * 16 + 8 * p;
    const float4* xp = (const float4*)(x + (size_t)br * IN_F + kb);
    float4 a = xp[0], b = xp[1];
    uint4 o;
    if (jj < 2) {                          // hi tiles: direct bf16 rounding
        o.x = pack_bf16x2(a.x, a.y);
        o.y = pack_bf16x2(a.z, a.w);
        o.z = pack_bf16x2(b.x, b.y);
        o.w = pack_bf16x2(b.z, b.w);
    } else {                               // lo tiles: residual after bf16
        o.x = pack_bf16x2(a.x - bf_round(a.x), a.y - bf_round(a.y));
        o.y = pack_bf16x2(a.z - bf_round(a.z), a.w - bf_round(a.w));
        o.z = pack_bf16x2(b.x - bf_round(b.x), b.y - bf_round(b.y));
        o.w = pack_bf16x2(b.z - bf_round(b.z), b.w - bf_round(b.w));
    }
    return o;
}

// ---------------------------------------------------------------------------
// HMMA GEMM (R6 mainloop, SPLITS=4) with fused B-fragment construction.
// Warp owns 16 output rows; A frags LDG'd from the int32 weight stream
// (depth-2 reg prefetch), converted in regs; B frags computed from x and
// double-buffered through smem. Epilogue transposed via smem.
// ---------------------------------------------------------------------------
__global__ void __launch_bounds__(THREADS) gemm_kernel(const int* __restrict__ W,
                                                       const float* __restrict__ x) {
    __shared__ __align__(16) uint32_t sb[2 * CKS * 256];   // 2 x 8 KB

    const int tid = threadIdx.x, wid = tid >> 5, l = tid & 31;
    const int g = l >> 2, t = l & 3;
    const int s = blockIdx.y;
    const int m0 = blockIdx.x * MTILE + wid * 16;
    const int ksbase = s * KSTEPS_SPLIT;

    const int* rowA  = W + (size_t)(m0 + g) * IN_F;
    const int* rowA8 = rowA + (size_t)8 * IN_F;

    // A prefetch ring (depth 2). Frag order: a0=[g][k0], a1=[g+8][k0], a2=[g][k8], a3=[g+8][k8]
    int2 ar[2][4];
#define LDA(i, buf) do {                                      \
        int _kk = (ksbase + (i)) * 16 + 2 * t;                \
        ar[buf][0] = *(const int2*)(rowA  + _kk);             \
        ar[buf][1] = *(const int2*)(rowA8 + _kk);             \
        ar[buf][2] = *(const int2*)(rowA  + _kk + 8);         \
        ar[buf][3] = *(const int2*)(rowA8 + _kk + 8);         \
    } while (0)

    float acc[16];
#pragma unroll
    for (int i = 0; i < 16; i++) acc[i] = 0.f;

    // Stage B chunk 0 (computed from x) into smem; A ksteps 0,1 into regs.
    uint4 stage[4];
#pragma unroll
    for (int j = 0; j < 4; j++) stage[j] = make_bstage(x, ksbase, j * 128 + tid);
#pragma unroll
    for (int j = 0; j < 4; j++) ((uint4*)sb)[j * 128 + tid] = stage[j];
    LDA(0, 0);
    LDA(1, 1);
    __syncthreads();

    int p = 0;
    for (int c = 0; c < NCHUNK; c++) {
        if (c + 1 < NCHUNK) {          // compute next B chunk into regs
#pragma unroll
            for (int j = 0; j < 4; j++)
                stage[j] = make_bstage(x, ksbase + (c + 1) * CKS, j * 128 + tid);
        }

        const uint32_t* bbuf = sb + p * (CKS * 256);
#pragma unroll
        for (int ksl = 0; ksl < CKS; ksl++) {
            int i = c * CKS + ksl;
            int buf = i & 1;
            uint32_t a[4];
#pragma unroll
            for (int q = 0; q < 4; q++)
                a[q] = pack_bf16x2((float)ar[buf][q].x, (float)ar[buf][q].y);
            if (i + 2 < KSTEPS_SPLIT) LDA(i + 2, buf);   // refill slot just consumed

            uint32_t bw[8];
#pragma unroll
            for (int r = 0; r < 8; r++) bw[r] = bbuf[ksl * 256 + r * 32 + l];

            mma16816(acc + 0,  a, bw[0], bw[1]);   // n-tile 0 (hi b0..7)
            mma16816(acc + 4,  a, bw[2], bw[3]);   // n-tile 1 (hi b8..15)
            mma16816(acc + 8,  a, bw[4], bw[5]);   // n-tile 2 (lo b0..7)
            mma16816(acc + 12, a, bw[6], bw[7]);   // n-tile 3 (lo b8..15)
        }

        if (c + 1 < NCHUNK) {
#pragma unroll
            for (int j = 0; j < 4; j++) ((uint4*)sb)[(p ^ 1) * 512 + j * 128 + tid] = stage[j];
        }
        __syncthreads();
        p ^= 1;
    }

    // Epilogue: hi + lo, transpose through smem (reuse sb), coalesced stores.
    // C frag: c0=[g][2t], c1=[g][2t+1], c2=[g+8][2t], c3=[g+8][2t+1]
    float* sep = (float*)sb;                       // [b][m_local] = 16 x 64 floats
#pragma unroll
    for (int j = 0; j < 2; j++) {
        int b0 = j * 8 + 2 * t;
        int ml = wid * 16 + g;
        sep[(b0)     * MTILE + ml]     = acc[j * 4 + 0] + acc[(j + 2) * 4 + 0];
        sep[(b0 + 1) * MTILE + ml]     = acc[j * 4 + 1] + acc[(j + 2) * 4 + 1];
        sep[(b0)     * MTILE + ml + 8] = acc[j * 4 + 2] + acc[(j + 2) * 4 + 2];
        sep[(b0 + 1) * MTILE + ml + 8] = acc[j * 4 + 3] + acc[(j + 2) * 4 + 3];
    }
    __syncthreads();

    float* pb = g_part + (size_t)s * (BATCH * OUT_F) + blockIdx.x * MTILE;
#pragma unroll
    for (int f = tid; f < BATCH * MTILE / 4; f += THREADS) {   // 256 float4s
        int b   = f >> 4;
        int seg = f & 15;
        float4 v = ((const float4*)sep)[f];
        *(float4*)(pb + (size_t)b * OUT_F + seg * 4) = v;
    }
}

// ---------------------------------------------------------------------------
// Reduce the 4 split partials (fixed order), apply scale + bias.
// ---------------------------------------------------------------------------
__global__ void __launch_bounds__(256) reduce_kernel(const float* __restrict__ scale,
                                                     const float* __restrict__ bias,
                                                     float* __restrict__ out) {
    const int NV = BATCH * OUT_F / 4;
    int e = blockIdx.x * blockDim.x + threadIdx.x;
    if (e >= NV) return;
    int o4 = e % (OUT_F / 4);

    float4 v[SPLITS];
#pragma unroll
    for (int s = 0; s < SPLITS; s++)
        v[s] = ((const float4*)g_part)[(size_t)s * NV + e];

    float4 sum;
    sum.x = (v[0].x + v[1].x) + (v[2].x + v[3].x);
    sum.y = (v[0].y + v[1].y) + (v[2].y + v[3].y);
    sum.z = (v[0].z + v[1].z) + (v[2].z + v[3].z);
    sum.w = (v[0].w + v[1].w) + (v[2].w + v[3].w);

    float4 sc = ((const float4*)scale)[o4];
    float4 bi = ((const float4*)bias)[o4];
    float4 r;
    r.x = fmaf(sum.x, sc.x, bi.x);
    r.y = fmaf(sum.y, sc.y, bi.y);
    r.z = fmaf(sum.z, sc.z, bi.z);
    r.w = fmaf(sum.w, sc.w, bi.w);
    ((float4*)out)[e] = r;
}

extern "C" void kernel_launch(void* const* d_in, const int* in_sizes, int n_in,
                              void* d_out, int out_size) {
    const float* x     = (const float*)d_in[0];
    const int*   W     = (const int*)d_in[1];
    const float* scale = (const float*)d_in[2];
    const float* bias  = (const float*)d_in[3];
    float*       out   = (float*)d_out;

    dim3 grid(OUT_F / MTILE, SPLITS);          // 172 x 4 = 688 CTAs
    gemm_kernel<<<grid, THREADS>>>(W, x);

    int nv = BATCH * OUT_F / 4;
    reduce_kernel<<<(nv + 255) / 256, 256>>>(scale, bias, out);
}

// round 14
// speedup vs baseline: 1.3317x; 1.3317x over previous
#include <cuda_runtime.h>
#include <cuda_bf16.h>
#include <stdint.h>

#define IN_F   4096
#define OUT_F  11008
#define BATCH  16
#define SPLITS 4
#define KSTEPS_TOT   (IN_F / 16)            // 256 k16-steps
#define KSTEPS_SPLIT (KSTEPS_TOT / SPLITS)  // 64
#define CKS    8                            // ksteps per smem chunk
#define NCHUNK (KSTEPS_SPLIT / CKS)         // 8
#define MTILE  64
#define THREADS 128
#define NXBLK  (OUT_F / MTILE)              // 172

// Static scratch (allocations forbidden). g_counter zero-initialized at load;
// each execution returns it to all-zeros (last CTA per stripe resets).
__device__ __align__(16) uint32_t g_bfrag[KSTEPS_TOT * 256];      // [ks][reg(8)][lane(32)]
__device__ __align__(16) float    g_part[SPLITS * BATCH * OUT_F]; // [s][b][o]
__device__ int g_counter[NXBLK];

// Pack two floats into one bf16x2 reg (low = first).
__device__ __forceinline__ uint32_t pack_bf16x2(float ev, float od) {
    __nv_bfloat162 h = __floats2bfloat162_rn(ev, od);   // .x = ev (low), .y = od (high)
    return *(uint32_t*)&h;
}

// m16n8k16 row.col bf16 MMA, fp32 accumulate in place.
__device__ __forceinline__ void mma16816(float* c, const uint32_t* a, uint32_t b0, uint32_t b1) {
    asm volatile(
        "mma.sync.aligned.m16n8k16.row.col.f32.bf16.bf16.f32 "
        "{%0,%1,%2,%3}, {%4,%5,%6,%7}, {%8,%9}, {%0,%1,%2,%3};"
        : "+f"(c[0]), "+f"(c[1]), "+f"(c[2]), "+f"(c[3])
        : "r"(a[0]), "r"(a[1]), "r"(a[2]), "r"(a[3]), "r"(b0), "r"(b1));
}

// ---------------------------------------------------------------------------
// Kernel 1: build B fragments, one thread per fragment reg (65536 threads).
// idx = ks*256 + r*32 + l.  r = j*2 + p:  n-tile j (0,1 hi / 2,3 lo of batch
// rows (j&1)*8+g),  p selects k0/k8 halves.  Fully coalesced 128B stores.
// ---------------------------------------------------------------------------
__global__ void prep_kernel(const float* __restrict__ x) {
    int idx = blockIdx.x * blockDim.x + threadIdx.x;   // KSTEPS_TOT*256 = 65536
    int l  = idx & 31;
    int r  = (idx >> 5) & 7;
    int ks = idx >> 8;
    int g = l >> 2, t = l & 3;
    int j = r >> 1, p = r & 1;
    int br = (j & 1) * 8 + g;
    int k  = ks * 16 + 2 * t + 8 * p;

    float2 v = *(const float2*)(x + (size_t)br * IN_F + k);
    float h0 = __bfloat162float(__float2bfloat16(v.x));
    float h1 = __bfloat162float(__float2bfloat16(v.y));
    uint32_t out;
    if (j < 2) out = pack_bf16x2(h0, h1);              // hi part
    else       out = pack_bf16x2(v.x - h0, v.y - h1);  // lo residual
    g_bfrag[idx] = out;
}

// ---------------------------------------------------------------------------
// Kernel 2: HMMA GEMM (R12 mainloop, SPLITS=4) + FUSED cross-split reduction.
// Warp owns 16 output rows; A frags LDG'd from the int32 weight stream
// (depth-2 reg prefetch), converted in regs; B frags from double-buffered
// smem. The last CTA per output stripe sums the 4 partials, applies
// scale+bias, writes the final output (threadfence-reduction pattern).
// ---------------------------------------------------------------------------
__global__ void __launch_bounds__(THREADS) gemm_kernel(const int* __restrict__ W,
                                                       const float* __restrict__ scale,
                                                       const float* __restrict__ bias,
                                                       float* __restrict__ out) {
    __shared__ __align__(16) uint32_t sb[2 * CKS * 256];   // 2 x 8 KB
    __shared__ int s_ticket;

    const int tid = threadIdx.x, wid = tid >> 5, l = tid & 31;
    const int g = l >> 2, t = l & 3;
    const int s = blockIdx.y;
    const int m0 = blockIdx.x * MTILE + wid * 16;
    const int ksbase = s * KSTEPS_SPLIT;

    const int* rowA  = W + (size_t)(m0 + g) * IN_F;
    const int* rowA8 = rowA + (size_t)8 * IN_F;

    // A prefetch ring (depth 2). Frag order: a0=[g][k0], a1=[g+8][k0], a2=[g][k8], a3=[g+8][k8]
    int2 ar[2][4];
#define LDA(i, buf) do {                                      \
        int _kk = (ksbase + (i)) * 16 + 2 * t;                \
        ar[buf][0] = *(const int2*)(rowA  + _kk);             \
        ar[buf][1] = *(const int2*)(rowA8 + _kk);             \
        ar[buf][2] = *(const int2*)(rowA  + _kk + 8);         \
        ar[buf][3] = *(const int2*)(rowA8 + _kk + 8);         \
    } while (0)

    const uint4* bsrc = (const uint4*)(g_bfrag + ksbase * 256);

    float acc[16];
#pragma unroll
    for (int i = 0; i < 16; i++) acc[i] = 0.f;

    // Preload B chunk 0 into smem, A ksteps 0,1 into regs.
    uint4 stage[4];
#pragma unroll
    for (int j = 0; j < 4; j++) stage[j] = bsrc[j * 128 + tid];
#pragma unroll
    for (int j = 0; j < 4; j++) ((uint4*)sb)[j * 128 + tid] = stage[j];
    LDA(0, 0);
    LDA(1, 1);
    __syncthreads();

    int p = 0;
    for (int c = 0; c < NCHUNK; c++) {
        if (c + 1 < NCHUNK) {          // prefetch next B chunk into regs
#pragma unroll
            for (int j = 0; j < 4; j++) stage[j] = bsrc[(c + 1) * 512 + j * 128 + tid];
        }

        const uint32_t* bbuf = sb + p * (CKS * 256);
#pragma unroll
        for (int ksl = 0; ksl < CKS; ksl++) {
            int i = c * CKS + ksl;
            int buf = i & 1;
            uint32_t a[4];
#pragma unroll
            for (int q = 0; q < 4; q++)
                a[q] = pack_bf16x2((float)ar[buf][q].x, (float)ar[buf][q].y);
            if (i + 2 < KSTEPS_SPLIT) LDA(i + 2, buf);   // refill slot just consumed

            uint32_t bw[8];
#pragma unroll
            for (int r = 0; r < 8; r++) bw[r] = bbuf[ksl * 256 + r * 32 + l];

            mma16816(acc + 0,  a, bw[0], bw[1]);   // n-tile 0 (hi b0..7)
            mma16816(acc + 4,  a, bw[2], bw[3]);   // n-tile 1 (hi b8..15)
            mma16816(acc + 8,  a, bw[4], bw[5]);   // n-tile 2 (lo b0..7)
            mma16816(acc + 12, a, bw[6], bw[7]);   // n-tile 3 (lo b8..15)
        }

        if (c + 1 < NCHUNK) {
#pragma unroll
            for (int j = 0; j < 4; j++) ((uint4*)sb)[(p ^ 1) * 512 + j * 128 + tid] = stage[j];
        }
        __syncthreads();
        p ^= 1;
    }

    // Epilogue: hi + lo, transpose through smem (reuse sb), coalesced stores.
    float* sep = (float*)sb;                       // [b][m_local] = 16 x 64 floats
#pragma unroll
    for (int j = 0; j < 2; j++) {
        int b0 = j * 8 + 2 * t;
        int ml = wid * 16 + g;
        sep[(b0)     * MTILE + ml]     = acc[j * 4 + 0] + acc[(j + 2) * 4 + 0];
        sep[(b0 + 1) * MTILE + ml]     = acc[j * 4 + 1] + acc[(j + 2) * 4 + 1];
        sep[(b0)     * MTILE + ml + 8] = acc[j * 4 + 2] + acc[(j + 2) * 4 + 2];
        sep[(b0 + 1) * MTILE + ml + 8] = acc[j * 4 + 3] + acc[(j + 2) * 4 + 3];
    }
    __syncthreads();

    float* pb = g_part + (size_t)s * (BATCH * OUT_F) + blockIdx.x * MTILE;
#pragma unroll
    for (int f = tid; f < BATCH * MTILE / 4; f += THREADS) {   // 256 float4s
        int b   = f >> 4;
        int seg = f & 15;
        float4 v = ((const float4*)sep)[f];
        *(float4*)(pb + (size_t)b * OUT_F + seg * 4) = v;
    }

    // ---- Fused cross-split reduction (threadfence-reduction pattern) ----
    __threadfence();                         // release partial stores
    if (tid == 0) s_ticket = atomicAdd(&g_counter[blockIdx.x], 1);
    __syncthreads();
    if (s_ticket != SPLITS - 1) return;      // not the last arriver

    if (tid == 0) atomicExch(&g_counter[blockIdx.x], 0);   // reset for next replay
    __threadfence();                         // acquire before reading partials

    const int NV4 = OUT_F / 4;               // float4s per batch row
    const int o4base = blockIdx.x * (MTILE / 4);
#pragma unroll
    for (int f = tid; f < BATCH * MTILE / 4; f += THREADS) {
        int b   = f >> 4;
        int seg = f & 15;
        size_t idx4 = (size_t)b * NV4 + o4base + seg;
        float4 v0 = __ldcg((const float4*)g_part + idx4);
        float4 v1 = __ldcg((const float4*)g_part + (size_t)1 * BATCH * NV4 + idx4);
        float4 v2 = __ldcg((const float4*)g_part + (size_t)2 * BATCH * NV4 + idx4);
        float4 v3 = __ldcg((const float4*)g_part + (size_t)3 * BATCH * NV4 + idx4);
        float4 sum;
        sum.x = (v0.x + v1.x) + (v2.x + v3.x);
        sum.y = (v0.y + v1.y) + (v2.y + v3.y);
        sum.z = (v0.z + v1.z) + (v2.z + v3.z);
        sum.w = (v0.w + v1.w) + (v2.w + v3.w);
        float4 sc = ((const float4*)scale)[o4base + seg];
        float4 bi = ((const float4*)bias)[o4base + seg];
        float4 r;
        r.x = fmaf(sum.x, sc.x, bi.x);
        r.y = fmaf(sum.y, sc.y, bi.y);
        r.z = fmaf(sum.z, sc.z, bi.z);
        r.w = fmaf(sum.w, sc.w, bi.w);
        ((float4*)out)[idx4] = r;
    }
}

extern "C" void kernel_launch(void* const* d_in, const int* in_sizes, int n_in,
                              void* d_out, int out_size) {
    const float* x     = (const float*)d_in[0];
    const int*   W     = (const int*)d_in[1];
    const float* scale = (const float*)d_in[2];
    const float* bias  = (const float*)d_in[3];
    float*       out   = (float*)d_out;

    prep_kernel<<<(KSTEPS_TOT * 256) / 256, 256>>>(x);

    dim3 grid(NXBLK, SPLITS);                  // 172 x 4 = 688 CTAs
    gemm_kernel<<<grid, THREADS>>>(W, scale, bias, out);
}